// round 9
// baseline (speedup 1.0000x reference)
#include <cuda_runtime.h>
#include <cuda_bf16.h>

// Problem constants
#define BB 1024
#define TT 512
#define EMB 100
#define H1 128
#define H2 64
#define G1 512        // 4*H1
#define G2 256        // 4*H2
#define ROWS 8        // batch rows per recurrence CTA
#define NBLK 128      // 1024/8

typedef unsigned long long ull;

// ---------------- scratch (static device memory: allocation-free) ----------------
__device__ float g_W1I[EMB * G1];        // [k][j] j-fastest, for proj1
__device__ float g_W1H[32 * G1 * 4];     // [g][j][u] k-major groups (k=4g+u), recurrence l1
__device__ float g_W2I[H1 * G2];         // [k][j] j-fastest, for proj2
__device__ float g_W2H[16 * G2 * 4];     // [g][j][u], recurrence l2
__device__ float g_b1s[G1];
__device__ float g_b2s[G2];
__device__ float g_hs1[BB * TT * H1];            // [block][t][k*8+r]   (268 MB)
__device__ float g_xw1[(size_t)BB * TT * G1];    // [block][t][r][j]    (1 GB)
__device__ float g_xw2[(size_t)BB * TT * G2];    // [block][t][r][j]    (0.5 GB)
__device__ float g_hn[BB * H2];                  // [block][k*8+r]

// ---------------- helpers ----------------
__device__ __forceinline__ ull pack2(float lo, float hi) {
    ull r; asm("mov.b64 %0, {%1,%2};" : "=l"(r) : "f"(lo), "f"(hi)); return r;
}
__device__ __forceinline__ void unpack2(ull v, float& lo, float& hi) {
    asm("mov.b64 {%0,%1}, %2;" : "=f"(lo), "=f"(hi) : "l"(v));
}
__device__ __forceinline__ ull fma2(ull a, ull b, ull c) {
    ull d; asm("fma.rn.f32x2 %0, %1, %2, %3;" : "=l"(d) : "l"(a), "l"(b), "l"(c)); return d;
}
__device__ __forceinline__ float sigf(float x) {
    return __fdividef(1.f, 1.f + __expf(-x));
}
__device__ __forceinline__ float tanh_(float x) {
    return __fdividef(2.f, 1.f + __expf(-2.f * x)) - 1.f;
}

// recurrence k-slice: 8 rows (stride 8, packed) x 2 cols
__device__ __forceinline__ void kslice(const ulonglong2* __restrict__ uhx, int k,
                                       float wa, float wb,
                                       ull& A01, ull& A23, ull& A45, ull& A67,
                                       ull& B01, ull& B23, ull& B45, ull& B67) {
    ulonglong2 p0 = uhx[2 * k];
    ulonglong2 p1 = uhx[2 * k + 1];
    ull wa2 = pack2(wa, wa);
    ull wb2 = pack2(wb, wb);
    A01 = fma2(p0.x, wa2, A01); A23 = fma2(p0.y, wa2, A23);
    A45 = fma2(p1.x, wa2, A45); A67 = fma2(p1.y, wa2, A67);
    B01 = fma2(p0.x, wb2, B01); B23 = fma2(p0.y, wb2, B23);
    B45 = fma2(p1.x, wb2, B45); B67 = fma2(p1.y, wb2, B67);
}
#define KS(kk, wa, wb) kslice(uhx, (kk), (wa), (wb), A01, A23, A45, A67, B01, B23, B45, B67)
#define KSG(gg, w4a, w4b) do { \
    KS(4*(gg)+0, (w4a).x, (w4b).x); \
    KS(4*(gg)+1, (w4a).y, (w4b).y); \
    KS(4*(gg)+2, (w4a).z, (w4b).z); \
    KS(4*(gg)+3, (w4a).w, (w4b).w); } while (0)

// ---------------- prep: build packed weights ----------------
__global__ void prep_kernel(const float* __restrict__ W1ih, const float* __restrict__ W1hh,
                            const float* __restrict__ b1ih, const float* __restrict__ b1hh,
                            const float* __restrict__ W2ih, const float* __restrict__ W2hh,
                            const float* __restrict__ b2ih, const float* __restrict__ b2hh) {
    int idx = blockIdx.x * blockDim.x + threadIdx.x;
    if (idx < EMB * G1) {                 // 51200
        int k = idx >> 9, j = idx & 511;
        g_W1I[idx] = W1ih[j * EMB + k];
    }
    if (idx < 32 * G1 * 4) {              // 65536
        int u = idx & 3, j = (idx >> 2) & 511, g = idx >> 11;
        g_W1H[idx] = W1hh[j * H1 + 4 * g + u];
    }
    if (idx < H1 * G2) {                  // 32768
        int k = idx >> 8, j = idx & 255;
        g_W2I[idx] = W2ih[j * H1 + k];
    }
    if (idx < 16 * G2 * 4) {              // 16384
        int u = idx & 3, j = (idx >> 2) & 255, g = idx >> 10;
        g_W2H[idx] = W2hh[j * H2 + 4 * g + u];
    }
    if (idx < G1) g_b1s[idx] = b1ih[idx] + b1hh[idx];
    if (idx < G2) g_b2s[idx] = b2ih[idx] + b2hh[idx];
}

// ---------------- proj1: xw1[b,t,:] = X[b,t,:] @ W1_ih^T + b1  (batched GEMM) ----------------
// CTA tile: 8 b x 4 t (32 rows) x 512 cols, K=100. 256 threads, 2-way row-split.
// smem: sW [100][512] floats (204800 B) + hx [100][36] (14400 B)
#define P1_SMEM_FLOATS (EMB * G1 + EMB * 36)

__global__ void __launch_bounds__(256, 1) proj1_kernel(const float* __restrict__ X) {
    extern __shared__ float sm[];
    float* sW = sm;
    float* hx = sW + EMB * G1;

    const int tid = threadIdx.x;
    const int bb = blockIdx.x & 127;      // b-block
    const int tb = blockIdx.x >> 7;       // t-block
    const int b0 = bb * 8, t0 = tb * 4;

    const float4* Wg = (const float4*)g_W1I;
    float4* sW4 = (float4*)sW;
    for (int i = tid; i < EMB * G1 / 4; i += 256) sW4[i] = __ldg(Wg + i);

    // stage X transposed: hx[k*36 + row], row = tl*8 + bl
    for (int idx = tid; idx < 32 * EMB; idx += 256) {
        int row = idx / EMB, k = idx - row * EMB;
        int bl = row & 7, tl = row >> 3;
        hx[k * 36 + row] = __ldg(X + ((size_t)(b0 + bl) * TT + (t0 + tl)) * EMB + k);
    }
    __syncthreads();

    const int half = tid >> 7;            // rows half*16 .. +15
    const int lane = tid & 127;
    const int j0 = lane * 4;

    float4 bv = *(const float4*)(g_b1s + j0);
    ull acc[4][8];
    #pragma unroll
    for (int u = 0; u < 8; ++u) {
        acc[0][u] = pack2(bv.x, bv.x);
        acc[1][u] = pack2(bv.y, bv.y);
        acc[2][u] = pack2(bv.z, bv.z);
        acc[3][u] = pack2(bv.w, bv.w);
    }

    #pragma unroll 2
    for (int k = 0; k < EMB; ++k) {
        float4 w = ((const float4*)(sW + k * G1))[lane];
        const ulonglong2* xp = (const ulonglong2*)(hx + k * 36 + half * 16);
        ulonglong2 x0 = xp[0], x1 = xp[1], x2 = xp[2], x3 = xp[3];
        ull w2;
        w2 = pack2(w.x, w.x);
        acc[0][0] = fma2(x0.x, w2, acc[0][0]); acc[0][1] = fma2(x0.y, w2, acc[0][1]);
        acc[0][2] = fma2(x1.x, w2, acc[0][2]); acc[0][3] = fma2(x1.y, w2, acc[0][3]);
        acc[0][4] = fma2(x2.x, w2, acc[0][4]); acc[0][5] = fma2(x2.y, w2, acc[0][5]);
        acc[0][6] = fma2(x3.x, w2, acc[0][6]); acc[0][7] = fma2(x3.y, w2, acc[0][7]);
        w2 = pack2(w.y, w.y);
        acc[1][0] = fma2(x0.x, w2, acc[1][0]); acc[1][1] = fma2(x0.y, w2, acc[1][1]);
        acc[1][2] = fma2(x1.x, w2, acc[1][2]); acc[1][3] = fma2(x1.y, w2, acc[1][3]);
        acc[1][4] = fma2(x2.x, w2, acc[1][4]); acc[1][5] = fma2(x2.y, w2, acc[1][5]);
        acc[1][6] = fma2(x3.x, w2, acc[1][6]); acc[1][7] = fma2(x3.y, w2, acc[1][7]);
        w2 = pack2(w.z, w.z);
        acc[2][0] = fma2(x0.x, w2, acc[2][0]); acc[2][1] = fma2(x0.y, w2, acc[2][1]);
        acc[2][2] = fma2(x1.x, w2, acc[2][2]); acc[2][3] = fma2(x1.y, w2, acc[2][3]);
        acc[2][4] = fma2(x2.x, w2, acc[2][4]); acc[2][5] = fma2(x2.y, w2, acc[2][5]);
        acc[2][6] = fma2(x3.x, w2, acc[2][6]); acc[2][7] = fma2(x3.y, w2, acc[2][7]);
        w2 = pack2(w.w, w.w);
        acc[3][0] = fma2(x0.x, w2, acc[3][0]); acc[3][1] = fma2(x0.y, w2, acc[3][1]);
        acc[3][2] = fma2(x1.x, w2, acc[3][2]); acc[3][3] = fma2(x1.y, w2, acc[3][3]);
        acc[3][4] = fma2(x2.x, w2, acc[3][4]); acc[3][5] = fma2(x2.y, w2, acc[3][5]);
        acc[3][6] = fma2(x3.x, w2, acc[3][6]); acc[3][7] = fma2(x3.y, w2, acc[3][7]);
    }

    // write out: per row, 4 consecutive cols as one float4 (coalesced STG.128)
    #pragma unroll
    for (int u = 0; u < 8; ++u) {
        float lo0, hi0, lo1, hi1, lo2, hi2, lo3, hi3;
        unpack2(acc[0][u], lo0, hi0);
        unpack2(acc[1][u], lo1, hi1);
        unpack2(acc[2][u], lo2, hi2);
        unpack2(acc[3][u], lo3, hi3);
        int r0 = half * 16 + 2 * u;
        int tl0 = r0 >> 3, bl0 = r0 & 7;
        size_t o0 = ((size_t)bb * TT + (t0 + tl0)) * 4096 + bl0 * G1 + j0;
        *(float4*)(g_xw1 + o0) = make_float4(lo0, lo1, lo2, lo3);
        int r1 = r0 + 1;
        int tl1 = r1 >> 3, bl1 = r1 & 7;
        size_t o1 = ((size_t)bb * TT + (t0 + tl1)) * 4096 + bl1 * G1 + j0;
        *(float4*)(g_xw1 + o1) = make_float4(hi0, hi1, hi2, hi3);
    }
}

// ---------------- proj2: xw2[b,t,:] = hs1[b,t,:] @ W2_ih^T + b2 ----------------
// CTA tile: 8 b x 4 t (32 rows) x 256 cols, K=128. 256 threads, 4-way row-split.
// smem: sW [128][256] (131072 B) + hx [128][36] (18432 B)
#define P2_SMEM_FLOATS (H1 * G2 + H1 * 36)

__global__ void __launch_bounds__(256, 1) proj2_kernel() {
    extern __shared__ float sm[];
    float* sW = sm;
    float* hx = sW + H1 * G2;

    const int tid = threadIdx.x;
    const int bb = blockIdx.x & 127;
    const int tb = blockIdx.x >> 7;
    const int t0 = tb * 4;

    const float4* Wg = (const float4*)g_W2I;
    float4* sW4 = (float4*)sW;
    for (int i = tid; i < H1 * G2 / 4; i += 256) sW4[i] = __ldg(Wg + i);

    // stage hs1 tile: source [bb][t0+tl][k*8+bl] -> hx[k*36 + tl*8 + bl]
    const float* src = g_hs1 + (size_t)bb * TT * 1024;
    for (int idx = tid; idx < 4096; idx += 256) {
        int tl = idx >> 10, rem = idx & 1023;
        int k = rem >> 3, bl = rem & 7;
        hx[k * 36 + tl * 8 + bl] = __ldg(src + (size_t)(t0 + tl) * 1024 + rem);
    }
    __syncthreads();

    const int q = tid >> 6;               // rows q*8 .. q*8+7
    const int lane = tid & 63;
    const int j0 = lane * 4;

    float4 bv = *(const float4*)(g_b2s + j0);
    ull acc[4][4];
    #pragma unroll
    for (int u = 0; u < 4; ++u) {
        acc[0][u] = pack2(bv.x, bv.x);
        acc[1][u] = pack2(bv.y, bv.y);
        acc[2][u] = pack2(bv.z, bv.z);
        acc[3][u] = pack2(bv.w, bv.w);
    }

    #pragma unroll 2
    for (int k = 0; k < H1; ++k) {
        float4 w = ((const float4*)(sW + k * G2))[lane];
        const ulonglong2* xp = (const ulonglong2*)(hx + k * 36 + q * 8);
        ulonglong2 x0 = xp[0], x1 = xp[1];
        ull w2;
        w2 = pack2(w.x, w.x);
        acc[0][0] = fma2(x0.x, w2, acc[0][0]); acc[0][1] = fma2(x0.y, w2, acc[0][1]);
        acc[0][2] = fma2(x1.x, w2, acc[0][2]); acc[0][3] = fma2(x1.y, w2, acc[0][3]);
        w2 = pack2(w.y, w.y);
        acc[1][0] = fma2(x0.x, w2, acc[1][0]); acc[1][1] = fma2(x0.y, w2, acc[1][1]);
        acc[1][2] = fma2(x1.x, w2, acc[1][2]); acc[1][3] = fma2(x1.y, w2, acc[1][3]);
        w2 = pack2(w.z, w.z);
        acc[2][0] = fma2(x0.x, w2, acc[2][0]); acc[2][1] = fma2(x0.y, w2, acc[2][1]);
        acc[2][2] = fma2(x1.x, w2, acc[2][2]); acc[2][3] = fma2(x1.y, w2, acc[2][3]);
        w2 = pack2(w.w, w.w);
        acc[3][0] = fma2(x0.x, w2, acc[3][0]); acc[3][1] = fma2(x0.y, w2, acc[3][1]);
        acc[3][2] = fma2(x1.x, w2, acc[3][2]); acc[3][3] = fma2(x1.y, w2, acc[3][3]);
    }

    #pragma unroll
    for (int u = 0; u < 4; ++u) {
        float lo0, hi0, lo1, hi1, lo2, hi2, lo3, hi3;
        unpack2(acc[0][u], lo0, hi0);
        unpack2(acc[1][u], lo1, hi1);
        unpack2(acc[2][u], lo2, hi2);
        unpack2(acc[3][u], lo3, hi3);
        int r0 = q * 8 + 2 * u;             // tl = q, bl = r0 & 7
        size_t o0 = ((size_t)bb * TT + (t0 + q)) * 2048 + (r0 & 7) * G2 + j0;
        *(float4*)(g_xw2 + o0) = make_float4(lo0, lo1, lo2, lo3);
        size_t o1 = o0 + G2;                // bl+1
        *(float4*)(g_xw2 + o1) = make_float4(hi0, hi1, hi2, hi3);
    }
}

// ---------------- lstm1 recurrence: K=128 (h only), xw1 streamed ----------------
// smem: sW[23 groups * 2048] (188416 B) | hx[128*8] (4096 B) | gshA+gshB (32768 B) = 225280 B
#define L1_SG 23
#define SMEM1_FLOATS (L1_SG * G1 * 4 + H1 * ROWS + 2 * ROWS * G1)

__global__ void __launch_bounds__(512, 1) lstm1_rec_kernel() {
    extern __shared__ float sm[];
    float* sW   = sm;
    float* hx   = sW + L1_SG * G1 * 4;     // [k][r], k=0..127
    float* gshA = hx + H1 * ROWS;
    float* gshB = gshA + ROWS * G1;

    const int tid = threadIdx.x;
    const int bid = blockIdx.x;
    const int j0 = tid & 255, j1 = j0 + 256;
    const bool half0 = (tid < 256);

    const float4* WH4 = (const float4*)g_W1H;
    float4* sW4 = (float4*)sW;
    for (int i = tid; i < L1_SG * G1; i += 512) sW4[i] = WH4[i];
    for (int i = tid; i < H1 * ROWS; i += 512) hx[i] = 0.f;

    const int an = tid & 127;
    const int ar = tid >> 7;               // 0..3 -> rows ar, ar+4
    float c0 = 0.f, c1 = 0.f;

    const ulonglong2* uhx = (const ulonglong2*)hx;
    float4* hx4 = (float4*)hx;
    float* gout = g_hs1 + (size_t)bid * TT * 1024;
    const float* xwb = g_xw1 + (size_t)bid * TT * 4096;
    float* gsh = half0 ? gshA : gshB;
    __syncthreads();

    for (int t = 0; t < TT; ++t) {
        __syncthreads();                   // h(t-1) visible; gsh consumed
        if (t > 0 && tid < 256)
            ((float4*)(gout + (size_t)(t - 1) * 1024))[tid] = hx4[tid];

        ull A01 = pack2(0.f, 0.f), A23 = A01, A45 = A01, A67 = A01;
        ull B01 = A01, B23 = A01, B45 = A01, B67 = A01;
        float xa[8], xb[8];

        if (half0) {
            // issue xw loads early; consumed after the k-loop
            const float* xr = xwb + (size_t)t * 4096;
            #pragma unroll
            for (int r = 0; r < 8; ++r) { xa[r] = __ldg(xr + r * G1 + j0); xb[r] = __ldg(xr + r * G1 + j1); }
            // groups 0..15 from smem
            #pragma unroll 4
            for (int gi = 0; gi < 16; ++gi) {
                float4 wa = sW4[gi * G1 + j0];
                float4 wb = sW4[gi * G1 + j1];
                KSG(gi, wa, wb);
            }
        } else {
            // groups 16..22 smem + 23..31 streamed, double-buffered
            float4 bufA[4], bufB[4];
            bufA[0] = __ldg(WH4 + 23 * G1 + j0); bufA[1] = __ldg(WH4 + 23 * G1 + j1);
            bufA[2] = __ldg(WH4 + 24 * G1 + j0); bufA[3] = __ldg(WH4 + 24 * G1 + j1);
            #pragma unroll 4
            for (int gi = 16; gi < L1_SG; ++gi) {
                float4 wa = sW4[gi * G1 + j0];
                float4 wb = sW4[gi * G1 + j1];
                KSG(gi, wa, wb);
            }
            bufB[0] = __ldg(WH4 + 25 * G1 + j0); bufB[1] = __ldg(WH4 + 25 * G1 + j1);
            bufB[2] = __ldg(WH4 + 26 * G1 + j0); bufB[3] = __ldg(WH4 + 26 * G1 + j1);
            KSG(23, bufA[0], bufA[1]);
            KSG(24, bufA[2], bufA[3]);
            bufA[0] = __ldg(WH4 + 27 * G1 + j0); bufA[1] = __ldg(WH4 + 27 * G1 + j1);
            bufA[2] = __ldg(WH4 + 28 * G1 + j0); bufA[3] = __ldg(WH4 + 28 * G1 + j1);
            KSG(25, bufB[0], bufB[1]);
            KSG(26, bufB[2], bufB[3]);
            bufB[0] = __ldg(WH4 + 29 * G1 + j0); bufB[1] = __ldg(WH4 + 29 * G1 + j1);
            bufB[2] = __ldg(WH4 + 30 * G1 + j0); bufB[3] = __ldg(WH4 + 30 * G1 + j1);
            KSG(27, bufA[0], bufA[1]);
            KSG(28, bufA[2], bufA[3]);
            bufA[0] = __ldg(WH4 + 31 * G1 + j0); bufA[1] = __ldg(WH4 + 31 * G1 + j1);
            KSG(29, bufB[0], bufB[1]);
            KSG(30, bufB[2], bufB[3]);
            KSG(31, bufA[0], bufA[1]);
            #pragma unroll
            for (int r = 0; r < 8; ++r) { xa[r] = 0.f; xb[r] = 0.f; }
        }

        float v0, v1;
        unpack2(A01, v0, v1); gsh[0 * G1 + j0] = v0 + xa[0]; gsh[1 * G1 + j0] = v1 + xa[1];
        unpack2(A23, v0, v1); gsh[2 * G1 + j0] = v0 + xa[2]; gsh[3 * G1 + j0] = v1 + xa[3];
        unpack2(A45, v0, v1); gsh[4 * G1 + j0] = v0 + xa[4]; gsh[5 * G1 + j0] = v1 + xa[5];
        unpack2(A67, v0, v1); gsh[6 * G1 + j0] = v0 + xa[6]; gsh[7 * G1 + j0] = v1 + xa[7];
        unpack2(B01, v0, v1); gsh[0 * G1 + j1] = v0 + xb[0]; gsh[1 * G1 + j1] = v1 + xb[1];
        unpack2(B23, v0, v1); gsh[2 * G1 + j1] = v0 + xb[2]; gsh[3 * G1 + j1] = v1 + xb[3];
        unpack2(B45, v0, v1); gsh[4 * G1 + j1] = v0 + xb[4]; gsh[5 * G1 + j1] = v1 + xb[5];
        unpack2(B67, v0, v1); gsh[6 * G1 + j1] = v0 + xb[6]; gsh[7 * G1 + j1] = v1 + xb[7];
        __syncthreads();

        {
            const float* ga = gshA + ar * G1;
            const float* gb = gshB + ar * G1;
            float ii = ga[an] + gb[an];
            float ff = ga[H1 + an] + gb[H1 + an];
            float gg = ga[2 * H1 + an] + gb[2 * H1 + an];
            float oo = ga[3 * H1 + an] + gb[3 * H1 + an];
            c0 = sigf(ff) * c0 + sigf(ii) * tanh_(gg);
            hx[an * ROWS + ar] = sigf(oo) * tanh_(c0);

            const float* ga2 = gshA + (ar + 4) * G1;
            const float* gb2 = gshB + (ar + 4) * G1;
            float i2 = ga2[an] + gb2[an];
            float f2 = ga2[H1 + an] + gb2[H1 + an];
            float g2 = ga2[2 * H1 + an] + gb2[2 * H1 + an];
            float o2 = ga2[3 * H1 + an] + gb2[3 * H1 + an];
            c1 = sigf(f2) * c1 + sigf(i2) * tanh_(g2);
            hx[an * ROWS + ar + 4] = sigf(o2) * tanh_(c1);
        }
    }
    __syncthreads();
    if (tid < 256)
        ((float4*)(gout + (size_t)(TT - 1) * 1024))[tid] = hx4[tid];
}

// ---------------- lstm2 recurrence: K=64 (h only), xw2 streamed, W all smem ----------------
// smem: sW[16*1024] (65536 B) | hx[64*8] (2048 B) | gshA+gshB (16384 B) = 83968 B
#define SMEM2_FLOATS (16 * G2 * 4 + H2 * ROWS + 2 * ROWS * G2)

__global__ void __launch_bounds__(256, 1) lstm2_rec_kernel() {
    extern __shared__ float sm[];
    float* sW   = sm;
    float* hx   = sW + 16 * G2 * 4;        // [k][r], k=0..63
    float* gshA = hx + H2 * ROWS;
    float* gshB = gshA + ROWS * G2;

    const int tid = threadIdx.x;
    const int bid = blockIdx.x;
    const int j0 = tid & 127, j1 = j0 + 128;
    const bool half0 = (tid < 128);

    const float4* WH4 = (const float4*)g_W2H;
    float4* sW4 = (float4*)sW;
    for (int i = tid; i < 16 * G2; i += 256) sW4[i] = WH4[i];
    for (int i = tid; i < H2 * ROWS; i += 256) hx[i] = 0.f;

    const int an = tid & 63;
    const int ar = tid >> 6;               // 0..3 -> rows ar, ar+4
    float c0 = 0.f, c1 = 0.f;

    const ulonglong2* uhx = (const ulonglong2*)hx;
    float4* hx4 = (float4*)hx;
    const float* xwb = g_xw2 + (size_t)bid * TT * 2048;
    float* gsh = half0 ? gshA : gshB;
    __syncthreads();

    for (int t = 0; t < TT; ++t) {
        __syncthreads();

        ull A01 = pack2(0.f, 0.f), A23 = A01, A45 = A01, A67 = A01;
        ull B01 = A01, B23 = A01, B45 = A01, B67 = A01;
        float xa[8], xb[8];

        if (half0) {
            const float* xr = xwb + (size_t)t * 2048;
            #pragma unroll
            for (int r = 0; r < 8; ++r) { xa[r] = __ldg(xr + r * G2 + j0); xb[r] = __ldg(xr + r * G2 + j1); }
            #pragma unroll 4
            for (int gi = 0; gi < 8; ++gi) {
                float4 wa = sW4[gi * G2 + j0];
                float4 wb = sW4[gi * G2 + j1];
                KSG(gi, wa, wb);
            }
        } else {
            #pragma unroll 4
            for (int gi = 8; gi < 16; ++gi) {
                float4 wa = sW4[gi * G2 + j0];
                float4 wb = sW4[gi * G2 + j1];
                KSG(gi, wa, wb);
            }
            #pragma unroll
            for (int r = 0; r < 8; ++r) { xa[r] = 0.f; xb[r] = 0.f; }
        }

        float v0, v1;
        unpack2(A01, v0, v1); gsh[0 * G2 + j0] = v0 + xa[0]; gsh[1 * G2 + j0] = v1 + xa[1];
        unpack2(A23, v0, v1); gsh[2 * G2 + j0] = v0 + xa[2]; gsh[3 * G2 + j0] = v1 + xa[3];
        unpack2(A45, v0, v1); gsh[4 * G2 + j0] = v0 + xa[4]; gsh[5 * G2 + j0] = v1 + xa[5];
        unpack2(A67, v0, v1); gsh[6 * G2 + j0] = v0 + xa[6]; gsh[7 * G2 + j0] = v1 + xa[7];
        unpack2(B01, v0, v1); gsh[0 * G2 + j1] = v0 + xb[0]; gsh[1 * G2 + j1] = v1 + xb[1];
        unpack2(B23, v0, v1); gsh[2 * G2 + j1] = v0 + xb[2]; gsh[3 * G2 + j1] = v1 + xb[3];
        unpack2(B45, v0, v1); gsh[4 * G2 + j1] = v0 + xb[4]; gsh[5 * G2 + j1] = v1 + xb[5];
        unpack2(B67, v0, v1); gsh[6 * G2 + j1] = v0 + xb[6]; gsh[7 * G2 + j1] = v1 + xb[7];
        __syncthreads();

        {
            const float* ga = gshA + ar * G2;
            const float* gb = gshB + ar * G2;
            float ii = ga[an] + gb[an];
            float ff = ga[H2 + an] + gb[H2 + an];
            float gg = ga[2 * H2 + an] + gb[2 * H2 + an];
            float oo = ga[3 * H2 + an] + gb[3 * H2 + an];
            c0 = sigf(ff) * c0 + sigf(ii) * tanh_(gg);
            hx[an * ROWS + ar] = sigf(oo) * tanh_(c0);

            const float* ga2 = gshA + (ar + 4) * G2;
            const float* gb2 = gshB + (ar + 4) * G2;
            float i2 = ga2[an] + gb2[an];
            float f2 = ga2[H2 + an] + gb2[H2 + an];
            float g2 = ga2[2 * H2 + an] + gb2[2 * H2 + an];
            float o2 = ga2[3 * H2 + an] + gb2[3 * H2 + an];
            c1 = sigf(f2) * c1 + sigf(i2) * tanh_(g2);
            hx[an * ROWS + ar + 4] = sigf(o2) * tanh_(c1);
        }
    }
    __syncthreads();
    if (tid < 128)
        ((float4*)g_hn)[bid * 128 + tid] = hx4[tid];
}

// ---------------- head: FC(64->32) relu, FC(32->1), sigmoid ----------------
__global__ void head_kernel(const float* __restrict__ fc1w, const float* __restrict__ fc1b,
                            const float* __restrict__ fc2w, const float* __restrict__ fc2b,
                            float* __restrict__ out) {
    __shared__ float sw1[32 * 64];
    __shared__ float sb1[32];
    __shared__ float sw2[32];
    int tid = threadIdx.x;  // 256
    for (int i = tid; i < 32 * 64; i += 256) sw1[i] = fc1w[i];
    if (tid < 32) { sb1[tid] = fc1b[tid]; sw2[tid] = fc2w[tid]; }
    __syncthreads();

    int b = blockIdx.x * 256 + tid;
    const float* h = g_hn + (size_t)(b >> 3) * (H2 * ROWS) + (b & 7);
    float hr[64];
    #pragma unroll
    for (int k = 0; k < 64; ++k) hr[k] = h[k * ROWS];
    float z = fc2b[0];
    #pragma unroll
    for (int i = 0; i < 32; ++i) {
        float s = sb1[i];
        const float* w = sw1 + i * 64;
        #pragma unroll
        for (int k = 0; k < 64; ++k) s += hr[k] * w[k];
        z += fmaxf(s, 0.f) * sw2[i];
    }
    out[b] = __fdividef(1.f, 1.f + __expf(-z));
}

// ---------------- launch ----------------
extern "C" void kernel_launch(void* const* d_in, const int* in_sizes, int n_in,
                              void* d_out, int out_size) {
    const float* X    = (const float*)d_in[0];
    const float* W1ih = (const float*)d_in[1];
    const float* W1hh = (const float*)d_in[2];
    const float* b1ih = (const float*)d_in[3];
    const float* b1hh = (const float*)d_in[4];
    const float* W2ih = (const float*)d_in[5];
    const float* W2hh = (const float*)d_in[6];
    const float* b2ih = (const float*)d_in[7];
    const float* b2hh = (const float*)d_in[8];
    const float* fc1w = (const float*)d_in[9];
    const float* fc1b = (const float*)d_in[10];
    const float* fc2w = (const float*)d_in[11];
    const float* fc2b = (const float*)d_in[12];
    float* out = (float*)d_out;

    const int smemP1 = P1_SMEM_FLOATS * (int)sizeof(float);  // 219200
    const int smemP2 = P2_SMEM_FLOATS * (int)sizeof(float);  // 149504
    const int smem1  = SMEM1_FLOATS * (int)sizeof(float);    // 225280
    const int smem2  = SMEM2_FLOATS * (int)sizeof(float);    // 83968
    cudaFuncSetAttribute(proj1_kernel, cudaFuncAttributeMaxDynamicSharedMemorySize, smemP1);
    cudaFuncSetAttribute(proj2_kernel, cudaFuncAttributeMaxDynamicSharedMemorySize, smemP2);
    cudaFuncSetAttribute(lstm1_rec_kernel, cudaFuncAttributeMaxDynamicSharedMemorySize, smem1);
    cudaFuncSetAttribute(lstm2_rec_kernel, cudaFuncAttributeMaxDynamicSharedMemorySize, smem2);

    prep_kernel<<<256, 256>>>(W1ih, W1hh, b1ih, b1hh, W2ih, W2hh, b2ih, b2hh);
    proj1_kernel<<<128 * 128, 256, smemP1>>>(X);
    lstm1_rec_kernel<<<NBLK, 512, smem1>>>();
    proj2_kernel<<<128 * 128, 256, smemP2>>>();
    lstm2_rec_kernel<<<NBLK, 256, smem2>>>();
    head_kernel<<<4, 256>>>(fc1w, fc1b, fc2w, fc2b, out);
}

// round 10
// speedup vs baseline: 1.2990x; 1.2990x over previous
#include <cuda_runtime.h>
#include <cuda_bf16.h>

// Problem constants
#define BB 1024
#define TT 512
#define EMB 100
#define H1 128
#define H2 64
#define G1 512        // 4*H1
#define G2 256        // 4*H2
#define ROWS 8        // batch rows per recurrence CTA
#define NBLK 128      // 1024/8

typedef unsigned long long ull;

// ---------------- scratch (static device memory: allocation-free) ----------------
__device__ float g_W1I[EMB * G1];        // [k][j] j-fastest, for proj1
__device__ float g_W1H[32 * G1 * 4];     // [g][j][u] k-major groups (k=4g+u), recurrence l1
__device__ float g_W2I[H1 * G2];         // [k][j] j-fastest, for proj2
__device__ float g_W2H[16 * G2 * 4];     // [g][j][u], recurrence l2
__device__ float g_b1s[G1];
__device__ float g_b2s[G2];
__device__ float g_hs1[BB * TT * H1];            // [block][t][k*8+r]   (268 MB)
__device__ float g_xw1[(size_t)BB * TT * G1];    // [block][t][r][j]    (1 GB)
__device__ float g_xw2[(size_t)BB * TT * G2];    // [block][t][r][j]    (0.5 GB)
__device__ float g_hn[BB * H2];                  // [block][k*8+r]

// ---------------- helpers ----------------
__device__ __forceinline__ ull pack2(float lo, float hi) {
    ull r; asm("mov.b64 %0, {%1,%2};" : "=l"(r) : "f"(lo), "f"(hi)); return r;
}
__device__ __forceinline__ void unpack2(ull v, float& lo, float& hi) {
    asm("mov.b64 {%0,%1}, %2;" : "=f"(lo), "=f"(hi) : "l"(v));
}
__device__ __forceinline__ ull fma2(ull a, ull b, ull c) {
    ull d; asm("fma.rn.f32x2 %0, %1, %2, %3;" : "=l"(d) : "l"(a), "l"(b), "l"(c)); return d;
}
__device__ __forceinline__ float sigf(float x) {
    return __fdividef(1.f, 1.f + __expf(-x));
}
__device__ __forceinline__ float tanh_(float x) {
    return __fdividef(2.f, 1.f + __expf(-2.f * x)) - 1.f;
}

// recurrence k-slice: 8 rows (stride 8, packed) x 2 cols
__device__ __forceinline__ void kslice(const ulonglong2* __restrict__ uhx, int k,
                                       float wa, float wb,
                                       ull& A01, ull& A23, ull& A45, ull& A67,
                                       ull& B01, ull& B23, ull& B45, ull& B67) {
    ulonglong2 p0 = uhx[2 * k];
    ulonglong2 p1 = uhx[2 * k + 1];
    ull wa2 = pack2(wa, wa);
    ull wb2 = pack2(wb, wb);
    A01 = fma2(p0.x, wa2, A01); A23 = fma2(p0.y, wa2, A23);
    A45 = fma2(p1.x, wa2, A45); A67 = fma2(p1.y, wa2, A67);
    B01 = fma2(p0.x, wb2, B01); B23 = fma2(p0.y, wb2, B23);
    B45 = fma2(p1.x, wb2, B45); B67 = fma2(p1.y, wb2, B67);
}
#define KS(kk, wa, wb) kslice(uhx, (kk), (wa), (wb), A01, A23, A45, A67, B01, B23, B45, B67)
#define KSG(gg, w4a, w4b) do { \
    KS(4*(gg)+0, (w4a).x, (w4b).x); \
    KS(4*(gg)+1, (w4a).y, (w4b).y); \
    KS(4*(gg)+2, (w4a).z, (w4b).z); \
    KS(4*(gg)+3, (w4a).w, (w4b).w); } while (0)

// proj k-slice: one weight scalar, 8 rows packed in 2 ull2
__device__ __forceinline__ void pslice(float w, ulonglong2 x0, ulonglong2 x1, ull* a) {
    ull w2 = pack2(w, w);
    a[0] = fma2(x0.x, w2, a[0]); a[1] = fma2(x0.y, w2, a[1]);
    a[2] = fma2(x1.x, w2, a[2]); a[3] = fma2(x1.y, w2, a[3]);
}

// ---------------- prep: build packed weights ----------------
__global__ void prep_kernel(const float* __restrict__ W1ih, const float* __restrict__ W1hh,
                            const float* __restrict__ b1ih, const float* __restrict__ b1hh,
                            const float* __restrict__ W2ih, const float* __restrict__ W2hh,
                            const float* __restrict__ b2ih, const float* __restrict__ b2hh) {
    int idx = blockIdx.x * blockDim.x + threadIdx.x;
    if (idx < EMB * G1) {                 // 51200
        int k = idx >> 9, j = idx & 511;
        g_W1I[idx] = W1ih[j * EMB + k];
    }
    if (idx < 32 * G1 * 4) {              // 65536
        int u = idx & 3, j = (idx >> 2) & 511, g = idx >> 11;
        g_W1H[idx] = W1hh[j * H1 + 4 * g + u];
    }
    if (idx < H1 * G2) {                  // 32768
        int k = idx >> 8, j = idx & 255;
        g_W2I[idx] = W2ih[j * H1 + k];
    }
    if (idx < 16 * G2 * 4) {              // 16384
        int u = idx & 3, j = (idx >> 2) & 255, g = idx >> 10;
        g_W2H[idx] = W2hh[j * H2 + 4 * g + u];
    }
    if (idx < G1) g_b1s[idx] = b1ih[idx] + b1hh[idx];
    if (idx < G2) g_b2s[idx] = b2ih[idx] + b2hh[idx];
}

// ---------------- proj1 (PERSISTENT): xw1 = X @ W1_ih^T + b1 ----------------
// grid=148, 512 threads, W staged ONCE. Tile: 8b x 4t (32 rows) x 512 cols.
// thread: lane (128 float4-cols) x rg (4 groups of 8 rows). smem: sW 200KB + hx 14.4KB
#define P1_TILES (128 * 128)
#define P1_SMEM_FLOATS (EMB * G1 + EMB * 36)

__global__ void __launch_bounds__(512, 1) proj1_kernel(const float* __restrict__ X) {
    extern __shared__ float sm[];
    float* sW = sm;
    float* hx = sW + EMB * G1;

    const int tid = threadIdx.x;
    const float4* Wg = (const float4*)g_W1I;
    float4* sW4 = (float4*)sW;
    for (int i = tid; i < EMB * G1 / 4; i += 512) sW4[i] = __ldg(Wg + i);

    const int lane = tid & 127;
    const int rg   = tid >> 7;            // 0..3: rows rg*8 .. rg*8+7 (tl=rg, bl=0..7)
    const int j0   = lane * 4;
    const float4 bv = *(const float4*)(g_b1s + j0);

    for (int tile = blockIdx.x; tile < P1_TILES; tile += gridDim.x) {
        const int bb = tile & 127, tb = tile >> 7;
        const int b0 = bb * 8, t0 = tb * 4;

        __syncthreads();                  // previous compute done (and W staged, first iter)
        for (int idx = tid; idx < 32 * EMB; idx += 512) {
            int row = idx / EMB, k = idx - row * EMB;
            int bl = row & 7, tl = row >> 3;
            hx[k * 36 + row] = __ldg(X + ((size_t)(b0 + bl) * TT + (t0 + tl)) * EMB + k);
        }
        __syncthreads();

        ull a0[4], a1[4], a2[4], a3[4];
        #pragma unroll
        for (int u = 0; u < 4; ++u) {
            a0[u] = pack2(bv.x, bv.x);
            a1[u] = pack2(bv.y, bv.y);
            a2[u] = pack2(bv.z, bv.z);
            a3[u] = pack2(bv.w, bv.w);
        }

        #pragma unroll 4
        for (int k = 0; k < EMB; ++k) {
            float4 w = sW4[k * 128 + lane];
            const ulonglong2* xp = (const ulonglong2*)(hx + k * 36 + rg * 8);
            ulonglong2 x0 = xp[0], x1 = xp[1];
            pslice(w.x, x0, x1, a0);
            pslice(w.y, x0, x1, a1);
            pslice(w.z, x0, x1, a2);
            pslice(w.w, x0, x1, a3);
        }

        // writeout: rows rg*8+u -> t=t0+rg, bl=u
        float* base = g_xw1 + ((size_t)bb * TT + (t0 + rg)) * 4096 + j0;
        #pragma unroll
        for (int m = 0; m < 4; ++m) {
            float l0, h0, l1, h1, l2, h2, l3, h3;
            unpack2(a0[m], l0, h0);
            unpack2(a1[m], l1, h1);
            unpack2(a2[m], l2, h2);
            unpack2(a3[m], l3, h3);
            *(float4*)(base + (2 * m) * G1)     = make_float4(l0, l1, l2, l3);
            *(float4*)(base + (2 * m + 1) * G1) = make_float4(h0, h1, h2, h3);
        }
    }
}

// ---------------- proj2 (PERSISTENT): xw2 = hs1 @ W2_ih^T + b2 ----------------
// grid=148, 512 threads. Tile: 8b x 8t (64 rows) x 256 cols, K=128.
// thread: lane (64 float4-cols) x rg (8 groups of 8 rows). smem: sW 128KB + hx 36KB
#define P2_TILES (128 * 64)
#define P2_SMEM_FLOATS (H1 * G2 + H1 * 72)

__global__ void __launch_bounds__(512, 1) proj2_kernel() {
    extern __shared__ float sm[];
    float* sW = sm;
    float* hx = sW + H1 * G2;

    const int tid = threadIdx.x;
    const float4* Wg = (const float4*)g_W2I;
    float4* sW4 = (float4*)sW;
    for (int i = tid; i < H1 * G2 / 4; i += 512) sW4[i] = __ldg(Wg + i);

    const int lane = tid & 63;
    const int rg   = tid >> 6;            // 0..7: rows rg*8..rg*8+7 (tl=rg, bl=0..7)
    const int j0   = lane * 4;
    const float4 bv = *(const float4*)(g_b2s + j0);

    for (int tile = blockIdx.x; tile < P2_TILES; tile += gridDim.x) {
        const int bb = tile & 127, tb = tile >> 7;
        const int t0 = tb * 8;
        const float* src = g_hs1 + (size_t)bb * TT * 1024;

        __syncthreads();
        // stage 64 rows x 128 k: source already [k*8+bl] per t-row
        for (int idx = tid; idx < 8192; idx += 512) {
            int tl = idx >> 10, rem = idx & 1023;
            int k = rem >> 3, bl = rem & 7;
            hx[k * 72 + tl * 8 + bl] = __ldg(src + (size_t)(t0 + tl) * 1024 + rem);
        }
        __syncthreads();

        ull a0[4], a1[4], a2[4], a3[4];
        #pragma unroll
        for (int u = 0; u < 4; ++u) {
            a0[u] = pack2(bv.x, bv.x);
            a1[u] = pack2(bv.y, bv.y);
            a2[u] = pack2(bv.z, bv.z);
            a3[u] = pack2(bv.w, bv.w);
        }

        #pragma unroll 4
        for (int k = 0; k < H1; ++k) {
            float4 w = sW4[k * 64 + lane];
            const ulonglong2* xp = (const ulonglong2*)(hx + k * 72 + rg * 8);
            ulonglong2 x0 = xp[0], x1 = xp[1];
            pslice(w.x, x0, x1, a0);
            pslice(w.y, x0, x1, a1);
            pslice(w.z, x0, x1, a2);
            pslice(w.w, x0, x1, a3);
        }

        float* base = g_xw2 + ((size_t)bb * TT + (t0 + rg)) * 2048 + j0;
        #pragma unroll
        for (int m = 0; m < 4; ++m) {
            float l0, h0, l1, h1, l2, h2, l3, h3;
            unpack2(a0[m], l0, h0);
            unpack2(a1[m], l1, h1);
            unpack2(a2[m], l2, h2);
            unpack2(a3[m], l3, h3);
            *(float4*)(base + (2 * m) * G2)     = make_float4(l0, l1, l2, l3);
            *(float4*)(base + (2 * m + 1) * G2) = make_float4(h0, h1, h2, h3);
        }
    }
}

// ---------------- lstm1 recurrence: K=128 (h only), xw1 streamed ----------------
// smem: sW[23 groups * 2048] (188416 B) | hx[128*8] (4096 B) | gshA+gshB (32768 B) = 225280 B
#define L1_SG 23
#define SMEM1_FLOATS (L1_SG * G1 * 4 + H1 * ROWS + 2 * ROWS * G1)

__global__ void __launch_bounds__(512, 1) lstm1_rec_kernel() {
    extern __shared__ float sm[];
    float* sW   = sm;
    float* hx   = sW + L1_SG * G1 * 4;     // [k][r], k=0..127
    float* gshA = hx + H1 * ROWS;
    float* gshB = gshA + ROWS * G1;

    const int tid = threadIdx.x;
    const int bid = blockIdx.x;
    const int j0 = tid & 255, j1 = j0 + 256;
    const bool half0 = (tid < 256);

    const float4* WH4 = (const float4*)g_W1H;
    float4* sW4 = (float4*)sW;
    for (int i = tid; i < L1_SG * G1; i += 512) sW4[i] = WH4[i];
    for (int i = tid; i < H1 * ROWS; i += 512) hx[i] = 0.f;

    const int an = tid & 127;
    const int ar = tid >> 7;               // 0..3 -> rows ar, ar+4
    float c0 = 0.f, c1 = 0.f;

    const ulonglong2* uhx = (const ulonglong2*)hx;
    float4* hx4 = (float4*)hx;
    float* gout = g_hs1 + (size_t)bid * TT * 1024;
    const float* xwb = g_xw1 + (size_t)bid * TT * 4096;
    float* gsh = half0 ? gshA : gshB;
    __syncthreads();

    for (int t = 0; t < TT; ++t) {
        __syncthreads();                   // h(t-1) visible; gsh consumed
        if (t > 0 && tid < 256)
            ((float4*)(gout + (size_t)(t - 1) * 1024))[tid] = hx4[tid];

        ull A01 = pack2(0.f, 0.f), A23 = A01, A45 = A01, A67 = A01;
        ull B01 = A01, B23 = A01, B45 = A01, B67 = A01;
        float xa[8], xb[8];

        if (half0) {
            // issue xw loads early; consumed after the k-loop
            const float* xr = xwb + (size_t)t * 4096;
            #pragma unroll
            for (int r = 0; r < 8; ++r) { xa[r] = __ldg(xr + r * G1 + j0); xb[r] = __ldg(xr + r * G1 + j1); }
            // groups 0..15 from smem
            #pragma unroll 4
            for (int gi = 0; gi < 16; ++gi) {
                float4 wa = sW4[gi * G1 + j0];
                float4 wb = sW4[gi * G1 + j1];
                KSG(gi, wa, wb);
            }
        } else {
            // groups 16..22 smem + 23..31 streamed, double-buffered
            float4 bufA[4], bufB[4];
            bufA[0] = __ldg(WH4 + 23 * G1 + j0); bufA[1] = __ldg(WH4 + 23 * G1 + j1);
            bufA[2] = __ldg(WH4 + 24 * G1 + j0); bufA[3] = __ldg(WH4 + 24 * G1 + j1);
            #pragma unroll 4
            for (int gi = 16; gi < L1_SG; ++gi) {
                float4 wa = sW4[gi * G1 + j0];
                float4 wb = sW4[gi * G1 + j1];
                KSG(gi, wa, wb);
            }
            bufB[0] = __ldg(WH4 + 25 * G1 + j0); bufB[1] = __ldg(WH4 + 25 * G1 + j1);
            bufB[2] = __ldg(WH4 + 26 * G1 + j0); bufB[3] = __ldg(WH4 + 26 * G1 + j1);
            KSG(23, bufA[0], bufA[1]);
            KSG(24, bufA[2], bufA[3]);
            bufA[0] = __ldg(WH4 + 27 * G1 + j0); bufA[1] = __ldg(WH4 + 27 * G1 + j1);
            bufA[2] = __ldg(WH4 + 28 * G1 + j0); bufA[3] = __ldg(WH4 + 28 * G1 + j1);
            KSG(25, bufB[0], bufB[1]);
            KSG(26, bufB[2], bufB[3]);
            bufB[0] = __ldg(WH4 + 29 * G1 + j0); bufB[1] = __ldg(WH4 + 29 * G1 + j1);
            bufB[2] = __ldg(WH4 + 30 * G1 + j0); bufB[3] = __ldg(WH4 + 30 * G1 + j1);
            KSG(27, bufA[0], bufA[1]);
            KSG(28, bufA[2], bufA[3]);
            bufA[0] = __ldg(WH4 + 31 * G1 + j0); bufA[1] = __ldg(WH4 + 31 * G1 + j1);
            KSG(29, bufB[0], bufB[1]);
            KSG(30, bufB[2], bufB[3]);
            KSG(31, bufA[0], bufA[1]);
            #pragma unroll
            for (int r = 0; r < 8; ++r) { xa[r] = 0.f; xb[r] = 0.f; }
        }

        float v0, v1;
        unpack2(A01, v0, v1); gsh[0 * G1 + j0] = v0 + xa[0]; gsh[1 * G1 + j0] = v1 + xa[1];
        unpack2(A23, v0, v1); gsh[2 * G1 + j0] = v0 + xa[2]; gsh[3 * G1 + j0] = v1 + xa[3];
        unpack2(A45, v0, v1); gsh[4 * G1 + j0] = v0 + xa[4]; gsh[5 * G1 + j0] = v1 + xa[5];
        unpack2(A67, v0, v1); gsh[6 * G1 + j0] = v0 + xa[6]; gsh[7 * G1 + j0] = v1 + xa[7];
        unpack2(B01, v0, v1); gsh[0 * G1 + j1] = v0 + xb[0]; gsh[1 * G1 + j1] = v1 + xb[1];
        unpack2(B23, v0, v1); gsh[2 * G1 + j1] = v0 + xb[2]; gsh[3 * G1 + j1] = v1 + xb[3];
        unpack2(B45, v0, v1); gsh[4 * G1 + j1] = v0 + xb[4]; gsh[5 * G1 + j1] = v1 + xb[5];
        unpack2(B67, v0, v1); gsh[6 * G1 + j1] = v0 + xb[6]; gsh[7 * G1 + j1] = v1 + xb[7];
        __syncthreads();

        {
            const float* ga = gshA + ar * G1;
            const float* gb = gshB + ar * G1;
            float ii = ga[an] + gb[an];
            float ff = ga[H1 + an] + gb[H1 + an];
            float gg = ga[2 * H1 + an] + gb[2 * H1 + an];
            float oo = ga[3 * H1 + an] + gb[3 * H1 + an];
            c0 = sigf(ff) * c0 + sigf(ii) * tanh_(gg);
            hx[an * ROWS + ar] = sigf(oo) * tanh_(c0);

            const float* ga2 = gshA + (ar + 4) * G1;
            const float* gb2 = gshB + (ar + 4) * G1;
            float i2 = ga2[an] + gb2[an];
            float f2 = ga2[H1 + an] + gb2[H1 + an];
            float g2 = ga2[2 * H1 + an] + gb2[2 * H1 + an];
            float o2 = ga2[3 * H1 + an] + gb2[3 * H1 + an];
            c1 = sigf(f2) * c1 + sigf(i2) * tanh_(g2);
            hx[an * ROWS + ar + 4] = sigf(o2) * tanh_(c1);
        }
    }
    __syncthreads();
    if (tid < 256)
        ((float4*)(gout + (size_t)(TT - 1) * 1024))[tid] = hx4[tid];
}

// ---------------- lstm2 recurrence: K=64 (h only), xw2 streamed, W all smem ----------------
// smem: sW[16*1024] (65536 B) | hx[64*8] (2048 B) | gshA+gshB (16384 B) = 83968 B
#define SMEM2_FLOATS (16 * G2 * 4 + H2 * ROWS + 2 * ROWS * G2)

__global__ void __launch_bounds__(256, 1) lstm2_rec_kernel() {
    extern __shared__ float sm[];
    float* sW   = sm;
    float* hx   = sW + 16 * G2 * 4;        // [k][r], k=0..63
    float* gshA = hx + H2 * ROWS;
    float* gshB = gshA + ROWS * G2;

    const int tid = threadIdx.x;
    const int bid = blockIdx.x;
    const int j0 = tid & 127, j1 = j0 + 128;
    const bool half0 = (tid < 128);

    const float4* WH4 = (const float4*)g_W2H;
    float4* sW4 = (float4*)sW;
    for (int i = tid; i < 16 * G2; i += 256) sW4[i] = WH4[i];
    for (int i = tid; i < H2 * ROWS; i += 256) hx[i] = 0.f;

    const int an = tid & 63;
    const int ar = tid >> 6;               // 0..3 -> rows ar, ar+4
    float c0 = 0.f, c1 = 0.f;

    const ulonglong2* uhx = (const ulonglong2*)hx;
    float4* hx4 = (float4*)hx;
    const float* xwb = g_xw2 + (size_t)bid * TT * 2048;
    float* gsh = half0 ? gshA : gshB;
    __syncthreads();

    for (int t = 0; t < TT; ++t) {
        __syncthreads();

        ull A01 = pack2(0.f, 0.f), A23 = A01, A45 = A01, A67 = A01;
        ull B01 = A01, B23 = A01, B45 = A01, B67 = A01;
        float xa[8], xb[8];

        if (half0) {
            const float* xr = xwb + (size_t)t * 2048;
            #pragma unroll
            for (int r = 0; r < 8; ++r) { xa[r] = __ldg(xr + r * G2 + j0); xb[r] = __ldg(xr + r * G2 + j1); }
            #pragma unroll 4
            for (int gi = 0; gi < 8; ++gi) {
                float4 wa = sW4[gi * G2 + j0];
                float4 wb = sW4[gi * G2 + j1];
                KSG(gi, wa, wb);
            }
        } else {
            #pragma unroll 4
            for (int gi = 8; gi < 16; ++gi) {
                float4 wa = sW4[gi * G2 + j0];
                float4 wb = sW4[gi * G2 + j1];
                KSG(gi, wa, wb);
            }
            #pragma unroll
            for (int r = 0; r < 8; ++r) { xa[r] = 0.f; xb[r] = 0.f; }
        }

        float v0, v1;
        unpack2(A01, v0, v1); gsh[0 * G2 + j0] = v0 + xa[0]; gsh[1 * G2 + j0] = v1 + xa[1];
        unpack2(A23, v0, v1); gsh[2 * G2 + j0] = v0 + xa[2]; gsh[3 * G2 + j0] = v1 + xa[3];
        unpack2(A45, v0, v1); gsh[4 * G2 + j0] = v0 + xa[4]; gsh[5 * G2 + j0] = v1 + xa[5];
        unpack2(A67, v0, v1); gsh[6 * G2 + j0] = v0 + xa[6]; gsh[7 * G2 + j0] = v1 + xa[7];
        unpack2(B01, v0, v1); gsh[0 * G2 + j1] = v0 + xb[0]; gsh[1 * G2 + j1] = v1 + xb[1];
        unpack2(B23, v0, v1); gsh[2 * G2 + j1] = v0 + xb[2]; gsh[3 * G2 + j1] = v1 + xb[3];
        unpack2(B45, v0, v1); gsh[4 * G2 + j1] = v0 + xb[4]; gsh[5 * G2 + j1] = v1 + xb[5];
        unpack2(B67, v0, v1); gsh[6 * G2 + j1] = v0 + xb[6]; gsh[7 * G2 + j1] = v1 + xb[7];
        __syncthreads();

        {
            const float* ga = gshA + ar * G2;
            const float* gb = gshB + ar * G2;
            float ii = ga[an] + gb[an];
            float ff = ga[H2 + an] + gb[H2 + an];
            float gg = ga[2 * H2 + an] + gb[2 * H2 + an];
            float oo = ga[3 * H2 + an] + gb[3 * H2 + an];
            c0 = sigf(ff) * c0 + sigf(ii) * tanh_(gg);
            hx[an * ROWS + ar] = sigf(oo) * tanh_(c0);

            const float* ga2 = gshA + (ar + 4) * G2;
            const float* gb2 = gshB + (ar + 4) * G2;
            float i2 = ga2[an] + gb2[an];
            float f2 = ga2[H2 + an] + gb2[H2 + an];
            float g2 = ga2[2 * H2 + an] + gb2[2 * H2 + an];
            float o2 = ga2[3 * H2 + an] + gb2[3 * H2 + an];
            c1 = sigf(f2) * c1 + sigf(i2) * tanh_(g2);
            hx[an * ROWS + ar + 4] = sigf(o2) * tanh_(c1);
        }
    }
    __syncthreads();
    if (tid < 128)
        ((float4*)g_hn)[bid * 128 + tid] = hx4[tid];
}

// ---------------- head: FC(64->32) relu, FC(32->1), sigmoid ----------------
__global__ void head_kernel(const float* __restrict__ fc1w, const float* __restrict__ fc1b,
                            const float* __restrict__ fc2w, const float* __restrict__ fc2b,
                            float* __restrict__ out) {
    __shared__ float sw1[32 * 64];
    __shared__ float sb1[32];
    __shared__ float sw2[32];
    int tid = threadIdx.x;  // 256
    for (int i = tid; i < 32 * 64; i += 256) sw1[i] = fc1w[i];
    if (tid < 32) { sb1[tid] = fc1b[tid]; sw2[tid] = fc2w[tid]; }
    __syncthreads();

    int b = blockIdx.x * 256 + tid;
    const float* h = g_hn + (size_t)(b >> 3) * (H2 * ROWS) + (b & 7);
    float hr[64];
    #pragma unroll
    for (int k = 0; k < 64; ++k) hr[k] = h[k * ROWS];
    float z = fc2b[0];
    #pragma unroll
    for (int i = 0; i < 32; ++i) {
        float s = sb1[i];
        const float* w = sw1 + i * 64;
        #pragma unroll
        for (int k = 0; k < 64; ++k) s += hr[k] * w[k];
        z += fmaxf(s, 0.f) * sw2[i];
    }
    out[b] = __fdividef(1.f, 1.f + __expf(-z));
}

// ---------------- launch ----------------
extern "C" void kernel_launch(void* const* d_in, const int* in_sizes, int n_in,
                              void* d_out, int out_size) {
    const float* X    = (const float*)d_in[0];
    const float* W1ih = (const float*)d_in[1];
    const float* W1hh = (const float*)d_in[2];
    const float* b1ih = (const float*)d_in[3];
    const float* b1hh = (const float*)d_in[4];
    const float* W2ih = (const float*)d_in[5];
    const float* W2hh = (const float*)d_in[6];
    const float* b2ih = (const float*)d_in[7];
    const float* b2hh = (const float*)d_in[8];
    const float* fc1w = (const float*)d_in[9];
    const float* fc1b = (const float*)d_in[10];
    const float* fc2w = (const float*)d_in[11];
    const float* fc2b = (const float*)d_in[12];
    float* out = (float*)d_out;

    const int smemP1 = P1_SMEM_FLOATS * (int)sizeof(float);  // 219200
    const int smemP2 = P2_SMEM_FLOATS * (int)sizeof(float);  // 167936
    const int smem1  = SMEM1_FLOATS * (int)sizeof(float);    // 225280
    const int smem2  = SMEM2_FLOATS * (int)sizeof(float);    // 83968
    cudaFuncSetAttribute(proj1_kernel, cudaFuncAttributeMaxDynamicSharedMemorySize, smemP1);
    cudaFuncSetAttribute(proj2_kernel, cudaFuncAttributeMaxDynamicSharedMemorySize, smemP2);
    cudaFuncSetAttribute(lstm1_rec_kernel, cudaFuncAttributeMaxDynamicSharedMemorySize, smem1);
    cudaFuncSetAttribute(lstm2_rec_kernel, cudaFuncAttributeMaxDynamicSharedMemorySize, smem2);

    prep_kernel<<<256, 256>>>(W1ih, W1hh, b1ih, b1hh, W2ih, W2hh, b2ih, b2hh);
    proj1_kernel<<<148, 512, smemP1>>>(X);
    lstm1_rec_kernel<<<NBLK, 512, smem1>>>();
    proj2_kernel<<<148, 512, smemP2>>>();
    lstm2_rec_kernel<<<NBLK, 256, smem2>>>();
    head_kernel<<<4, 256>>>(fc1w, fc1b, fc2w, fc2b, out);
}